// round 4
// baseline (speedup 1.0000x reference)
#include <cuda_runtime.h>
#include <math.h>

// Problem constants (fixed by the reference)
#define NB 2
#define NV 4
#define ND 48
#define HH 240
#define WW 320
#define NPIX (HH * WW)            // 76800
#define DEPTH_START 0.5f
#define DEPTH_STEP  (9.5f / 47.0f)

__device__ __forceinline__ void inv3(const float m[9], float o[9]) {
    float c00 = m[4] * m[8] - m[5] * m[7];
    float c01 = m[5] * m[6] - m[3] * m[8];
    float c02 = m[3] * m[7] - m[4] * m[6];
    float det = m[0] * c00 + m[1] * c01 + m[2] * c02;
    float id = 1.0f / det;
    o[0] = c00 * id;
    o[1] = (m[2] * m[7] - m[1] * m[8]) * id;
    o[2] = (m[1] * m[5] - m[2] * m[4]) * id;
    o[3] = c01 * id;
    o[4] = (m[0] * m[8] - m[2] * m[6]) * id;
    o[5] = (m[2] * m[3] - m[0] * m[5]) * id;
    o[6] = c02 * id;
    o[7] = (m[1] * m[6] - m[0] * m[7]) * id;
    o[8] = (m[0] * m[4] - m[1] * m[3]) * id;
}

__device__ __forceinline__ void mm3(const float a[9], const float b[9], float o[9]) {
#pragma unroll
    for (int i = 0; i < 3; i++)
#pragma unroll
        for (int j = 0; j < 3; j++)
            o[i * 3 + j] = a[i * 3 + 0] * b[0 * 3 + j]
                         + a[i * 3 + 1] * b[1 * 3 + j]
                         + a[i * 3 + 2] * b[2 * 3 + j];
}

__device__ __forceinline__ void mv3(const float a[9], const float v[3], float o[3]) {
#pragma unroll
    for (int i = 0; i < 3; i++)
        o[i] = a[i * 3 + 0] * v[0] + a[i * 3 + 1] * v[1] + a[i * 3 + 2] * v[2];
}

__global__ __launch_bounds__(256, 8) void sweep_kernel(
    const float* __restrict__ ys_dst,
    const float* __restrict__ xs_dst,
    const float* __restrict__ ys_src,
    const float* __restrict__ xs_src,
    const float* __restrict__ Kd,   // (8,3,3)
    const float* __restrict__ De,   // (8,4,4)
    const float* __restrict__ Ks,   // (8,3,3)
    const float* __restrict__ Se,   // (8,4,4)
    float* __restrict__ out)
{
    __shared__ float P[16];
    const int nv = blockIdx.y;

    // ---- per-block precompute by thread 0 only (keeps per-thread regs low) ----
    if (threadIdx.x == 0) {
        float kd[9], ks[9];
#pragma unroll
        for (int i = 0; i < 9; i++) { kd[i] = Kd[nv * 9 + i]; ks[i] = Ks[nv * 9 + i]; }

        // dst extrinsic [R t; 0 1]: R orthonormal -> inv(R) = R^T
        float Rdi[9], td[3], Rs[9], ts[3];
#pragma unroll
        for (int i = 0; i < 3; i++) {
#pragma unroll
            for (int j = 0; j < 3; j++) {
                Rdi[j * 3 + i] = De[nv * 16 + i * 4 + j];   // transpose
                Rs[i * 3 + j]  = Se[nv * 16 + i * 4 + j];
            }
            td[i] = De[nv * 16 + i * 4 + 3];
            ts[i] = Se[nv * 16 + i * 4 + 3];
        }

        float tdi[3];
        mv3(Rdi, td, tdi);
        tdi[0] = -tdi[0]; tdi[1] = -tdi[1]; tdi[2] = -tdi[2];

        // M3 = Rs * Rd^T ; Mt = Rs * tdi + ts
        float M3[9], Mt[3];
        mm3(Rs, Rdi, M3);
        mv3(Rs, tdi, Mt);
        Mt[0] += ts[0]; Mt[1] += ts[1]; Mt[2] += ts[2];

        // A = Ks * M3 * inv(Kd) ; b = Ks * Mt
        float Kdi[9];
        inv3(kd, Kdi);
        float T[9], A[9], b3[3];
        mm3(M3, Kdi, T);
        mm3(ks, T, A);
        mv3(ks, Mt, b3);

#pragma unroll
        for (int i = 0; i < 9; i++) P[i] = A[i];
        P[9]  = b3[0];
        P[10] = b3[1];
        P[11] = b3[2];
        P[12] = xs_dst[nv];
        P[13] = ys_dst[nv];
        P[14] = xs_src[nv];
        P[15] = ys_src[nv];
    }
    __syncthreads();

    const int pix = blockIdx.x * blockDim.x + threadIdx.x;
    if (pix >= NPIX) return;
    const int h = pix / WW;
    const int w = pix - h * WW;

    const float px = (float)w + P[12];
    const float py = (float)h + P[13];

    const float qx = P[0] * px + P[1] * py + P[2];
    const float qy = P[3] * px + P[4] * py + P[5];
    const float qz = P[6] * px + P[7] * py + P[8];
    const float bx = P[9], by = P[10], bz = P[11];
    const float xsrc = P[14], ysrc = P[15];

    // Output layout: sampling_maps (N,V,D,H,W,2) then mask (N,V,D,H,W)
    float2* __restrict__ maps = (float2*)out;
    float*  __restrict__ mask = out + (size_t)NB * NV * ND * NPIX * 2;

    const unsigned base = (unsigned)(nv * ND) * NPIX + (unsigned)pix;

#pragma unroll
    for (int d = 0; d < ND; d++) {
        const float depth = DEPTH_START + (float)d * DEPTH_STEP;
        const float zx = fmaf(depth, qx, bx);
        const float zy = fmaf(depth, qy, by);
        const float z  = fmaf(depth, qz, bz);
        const float zs = (fabsf(z) < 1e-6f) ? 1e-6f : z;
        const float r  = __fdividef(1.0f, zs);
        const float x  = zx * r - xsrc;
        const float y  = zy * r - ysrc;
        const float m  = (x >= 0.0f && x <= (float)(WW - 1) &&
                          y >= 0.0f && y <= (float)(HH - 1) &&
                          z > 1e-6f) ? 1.0f : 0.0f;
        const unsigned idx = base + (unsigned)d * NPIX;
        __stcs(&maps[idx], make_float2(x * m, y * m));
        __stcs(&mask[idx], m);
    }
}

extern "C" void kernel_launch(void* const* d_in, const int* in_sizes, int n_in,
                              void* d_out, int out_size) {
    const float* ys_dst = (const float*)d_in[0];
    const float* xs_dst = (const float*)d_in[1];
    const float* ys_src = (const float*)d_in[2];
    const float* xs_src = (const float*)d_in[3];
    // d_in[4] = height, d_in[5] = width — compile-time constants here
    const float* Kd = (const float*)d_in[6];
    const float* De = (const float*)d_in[7];
    const float* Ks = (const float*)d_in[8];
    const float* Se = (const float*)d_in[9];

    dim3 grid((NPIX + 255) / 256, NB * NV);
    sweep_kernel<<<grid, 256>>>(ys_dst, xs_dst, ys_src, xs_src,
                                Kd, De, Ks, Se, (float*)d_out);
}

// round 5
// speedup vs baseline: 1.0162x; 1.0162x over previous
#include <cuda_runtime.h>
#include <math.h>

// Problem constants (fixed by the reference)
#define NB 2
#define NV 4
#define ND 48
#define HH 240
#define WW 320
#define NPIX (HH * WW)            // 76800
#define DEPTH_START 0.5f
#define DEPTH_STEP  (9.5f / 47.0f)

// Per-(n,v) precomputed params: A[9], b[3], xs_dst, ys_dst, xs_src, ys_src
__device__ float g_params[NB * NV * 16];

__device__ __forceinline__ void inv3(const float m[9], float o[9]) {
    float c00 = m[4] * m[8] - m[5] * m[7];
    float c01 = m[5] * m[6] - m[3] * m[8];
    float c02 = m[3] * m[7] - m[4] * m[6];
    float det = m[0] * c00 + m[1] * c01 + m[2] * c02;
    float id = 1.0f / det;
    o[0] = c00 * id;
    o[1] = (m[2] * m[7] - m[1] * m[8]) * id;
    o[2] = (m[1] * m[5] - m[2] * m[4]) * id;
    o[3] = c01 * id;
    o[4] = (m[0] * m[8] - m[2] * m[6]) * id;
    o[5] = (m[2] * m[3] - m[0] * m[5]) * id;
    o[6] = c02 * id;
    o[7] = (m[1] * m[6] - m[0] * m[7]) * id;
    o[8] = (m[0] * m[4] - m[1] * m[3]) * id;
}

__device__ __forceinline__ void mm3(const float a[9], const float b[9], float o[9]) {
#pragma unroll
    for (int i = 0; i < 3; i++)
#pragma unroll
        for (int j = 0; j < 3; j++)
            o[i * 3 + j] = a[i * 3 + 0] * b[0 * 3 + j]
                         + a[i * 3 + 1] * b[1 * 3 + j]
                         + a[i * 3 + 2] * b[2 * 3 + j];
}

__device__ __forceinline__ void mv3(const float a[9], const float v[3], float o[3]) {
#pragma unroll
    for (int i = 0; i < 3; i++)
        o[i] = a[i * 3 + 0] * v[0] + a[i * 3 + 1] * v[1] + a[i * 3 + 2] * v[2];
}

__global__ void precompute_kernel(const float* __restrict__ ys_dst,
                                  const float* __restrict__ xs_dst,
                                  const float* __restrict__ ys_src,
                                  const float* __restrict__ xs_src,
                                  const float* __restrict__ Kd,   // (8,3,3)
                                  const float* __restrict__ De,   // (8,4,4)
                                  const float* __restrict__ Ks,   // (8,3,3)
                                  const float* __restrict__ Se) { // (8,4,4)
    int t = threadIdx.x;
    if (t >= NB * NV) return;

    float kd[9], ks[9];
#pragma unroll
    for (int i = 0; i < 9; i++) { kd[i] = Kd[t * 9 + i]; ks[i] = Ks[t * 9 + i]; }

    // dst extrinsic [R t; 0 1]: R orthonormal (QR, det=+1) -> inv(R) = R^T
    float Rdi[9], td[3], Rs[9], ts[3];
#pragma unroll
    for (int i = 0; i < 3; i++) {
#pragma unroll
        for (int j = 0; j < 3; j++) {
            Rdi[j * 3 + i] = De[t * 16 + i * 4 + j];   // transpose
            Rs[i * 3 + j]  = Se[t * 16 + i * 4 + j];
        }
        td[i] = De[t * 16 + i * 4 + 3];
        ts[i] = Se[t * 16 + i * 4 + 3];
    }

    float tdi[3];
    mv3(Rdi, td, tdi);
    tdi[0] = -tdi[0]; tdi[1] = -tdi[1]; tdi[2] = -tdi[2];

    // M3 = Rs * Rd^T ; Mt = Rs * tdi + ts
    float M3[9], Mt[3];
    mm3(Rs, Rdi, M3);
    mv3(Rs, tdi, Mt);
    Mt[0] += ts[0]; Mt[1] += ts[1]; Mt[2] += ts[2];

    // A = Ks * M3 * inv(Kd) ; b = Ks * Mt
    float Kdi[9];
    inv3(kd, Kdi);
    float T[9], A[9], b3[3];
    mm3(M3, Kdi, T);
    mm3(ks, T, A);
    mv3(ks, Mt, b3);

    float* P = g_params + t * 16;
#pragma unroll
    for (int i = 0; i < 9; i++) P[i] = A[i];
    P[9]  = b3[0];
    P[10] = b3[1];
    P[11] = b3[2];
    P[12] = xs_dst[t];
    P[13] = ys_dst[t];
    P[14] = xs_src[t];
    P[15] = ys_src[t];
}

__global__ __launch_bounds__(256, 8) void sweep_kernel(float* __restrict__ out) {
    __shared__ float P[16];
    const int nv = blockIdx.y;

    // --- param-independent setup first (overlaps the precompute grid via PDL) ---
    const int pix = blockIdx.x * blockDim.x + threadIdx.x;
    const int h = pix / WW;
    const int w = pix - h * WW;
    const unsigned base = (unsigned)(nv * ND) * NPIX + (unsigned)pix;

    float2* __restrict__ maps = (float2*)out;
    float*  __restrict__ mask = out + (size_t)NB * NV * ND * NPIX * 2;

    // Wait for the precompute grid to complete (PDL), then read its results.
    cudaGridDependencySynchronize();

    if (threadIdx.x < 16) P[threadIdx.x] = g_params[nv * 16 + threadIdx.x];
    __syncthreads();

    if (pix >= NPIX) return;

    const float px = (float)w + P[12];
    const float py = (float)h + P[13];

    const float qx = P[0] * px + P[1] * py + P[2];
    const float qy = P[3] * px + P[4] * py + P[5];
    const float qz = P[6] * px + P[7] * py + P[8];
    const float bx = P[9], by = P[10], bz = P[11];
    const float xsrc = P[14], ysrc = P[15];

#pragma unroll
    for (int d = 0; d < ND; d++) {
        const float depth = DEPTH_START + (float)d * DEPTH_STEP;
        const float zx = fmaf(depth, qx, bx);
        const float zy = fmaf(depth, qy, by);
        const float z  = fmaf(depth, qz, bz);
        const float zs = (fabsf(z) < 1e-6f) ? 1e-6f : z;
        const float r  = __fdividef(1.0f, zs);
        const float x  = zx * r - xsrc;
        const float y  = zy * r - ysrc;
        const float m  = (x >= 0.0f && x <= (float)(WW - 1) &&
                          y >= 0.0f && y <= (float)(HH - 1) &&
                          z > 1e-6f) ? 1.0f : 0.0f;
        const unsigned idx = base + (unsigned)d * NPIX;
        __stcs(&maps[idx], make_float2(x * m, y * m));
        __stcs(&mask[idx], m);
    }
}

extern "C" void kernel_launch(void* const* d_in, const int* in_sizes, int n_in,
                              void* d_out, int out_size) {
    const float* ys_dst = (const float*)d_in[0];
    const float* xs_dst = (const float*)d_in[1];
    const float* ys_src = (const float*)d_in[2];
    const float* xs_src = (const float*)d_in[3];
    // d_in[4] = height, d_in[5] = width — compile-time constants here
    const float* Kd = (const float*)d_in[6];
    const float* De = (const float*)d_in[7];
    const float* Ks = (const float*)d_in[8];
    const float* Se = (const float*)d_in[9];

    precompute_kernel<<<1, 32>>>(ys_dst, xs_dst, ys_src, xs_src, Kd, De, Ks, Se);

    // Launch sweep with Programmatic Dependent Launch so its launch latency
    // overlaps the precompute kernel; the device-side
    // cudaGridDependencySynchronize() provides the ordering.
    dim3 grid((NPIX + 255) / 256, NB * NV);
    cudaLaunchConfig_t cfg = {};
    cfg.gridDim = grid;
    cfg.blockDim = dim3(256, 1, 1);
    cfg.dynamicSmemBytes = 0;
    cfg.stream = 0;   // legacy default stream (same one the harness captures)
    cudaLaunchAttribute attrs[1];
    attrs[0].id = cudaLaunchAttributeProgrammaticStreamSerialization;
    attrs[0].val.programmaticStreamSerializationAllowed = 1;
    cfg.attrs = attrs;
    cfg.numAttrs = 1;
    cudaLaunchKernelEx(&cfg, sweep_kernel, (float*)d_out);
}